// round 16
// baseline (speedup 1.0000x reference)
#include <cuda_runtime.h>
#include <math.h>
#include <float.h>

// ---------------------------------------------------------------------------
// Problem constants
// ---------------------------------------------------------------------------
constexpr int N_   = 50000;
constexpr int IN_  = 128;
constexpr int HID_ = 64;
constexpr int H_   = 4;
constexpr int F_   = 256;    // H*D
constexpr int OUT_ = 16;
constexpr int SAH_ = 128;
constexpr int EMAX_ = 800000;

constexpr size_t NF = (size_t)N_ * F_;
constexpr int NH = N_ * H_;
constexpr int SC4N = 4 * N_;
constexpr int SCB4 = (SC4N + 255) / 256;
constexpr int WSB_N = (N_ + 127) / 128;
constexpr int W1HALF = (SAH_ * F_) / 2;

// ---------------------------------------------------------------------------
// Device scratch
// ---------------------------------------------------------------------------
__device__ float g_x[(size_t)N_ * HID_];
__device__ __align__(16) float g_el[6 * NH];
__device__ __align__(16) float g_er[6 * NH];
__device__ __align__(16) float g_wtab6[6][HID_ * 8];
__device__ float g_agg[6 * NF];
__device__ float g_emb[6 * NF];
__device__ float g_hl[2 * NF];
__device__ float g_wsum[3][4];
__device__ float g_beta[3][4];
__device__ unsigned int g_W1bf[3 * W1HALF];        // 3 W1 slots (L0, L1, final)

// Batched CSR scratch + CSR-ordered edge scores
__device__ int g_cnt4[SC4N];
__device__ int g_cursor4[SC4N];
__device__ int g_prefix[SC4N + 1];
__device__ int g_esrcF[4 * EMAX_];
__device__ __align__(16) float4 g_escA[4 * EMAX_]; // scores, slot A of edge's graph
__device__ __align__(16) float4 g_escB[4 * EMAX_]; // scores, slot B (graphs 0,1 only)
__device__ int g_bsum[SCB4];
__device__ int g_boff[SCB4];

struct G4 { const int* s[4]; const int* d[4]; int E[4]; };
struct LP {
    const float* W[2];
    const float* al[2];
    const float* ar[2];
    const float* bb[2];
    const float* b1[2];
    const float* w2[2];
};

// ---------------------------------------------------------------------------
// Low-level helpers
// ---------------------------------------------------------------------------
__device__ __forceinline__ unsigned int pack_bf2(float lo, float hi) {
    unsigned int r;
    asm("cvt.rn.bf16x2.f32 %0, %1, %2;" : "=r"(r) : "f"(hi), "f"(lo));
    return r;
}
__device__ __forceinline__ float tanh_fast(float x) {
    float r;
    asm("tanh.approx.f32 %0, %1;" : "=f"(r) : "f"(x));
    return r;
}
__device__ __forceinline__ void mma_bf16(float& d0, float& d1, float& d2, float& d3,
                                         unsigned int a0, unsigned int a1,
                                         unsigned int a2, unsigned int a3,
                                         unsigned int b0, unsigned int b1) {
    asm("mma.sync.aligned.m16n8k16.row.col.f32.bf16.bf16.f32 "
        "{%0,%1,%2,%3}, {%4,%5,%6,%7}, {%8,%9}, {%0,%1,%2,%3};"
        : "+f"(d0), "+f"(d1), "+f"(d2), "+f"(d3)
        : "r"(a0), "r"(a1), "r"(a2), "r"(a3), "r"(b0), "r"(b1));
}
__device__ __forceinline__ void fma2(unsigned long long& acc,
                                     unsigned long long a, unsigned long long b) {
    asm("fma.rn.f32x2 %0, %1, %2, %0;" : "+l"(acc) : "l"(a), "l"(b));
}
__device__ __forceinline__ unsigned long long packf2(float lo, float hi) {
    unsigned long long r;
    asm("mov.b64 %0, {%1,%2};" : "=l"(r) : "f"(lo), "f"(hi));
    return r;
}
__device__ __forceinline__ float unpack_sum(unsigned long long p) {
    float lo, hi;
    asm("mov.b64 {%0,%1}, %2;" : "=f"(lo), "=f"(hi) : "l"(p));
    return lo + hi;
}
__device__ __forceinline__ float2 unpack2(unsigned long long p) {
    float lo, hi;
    asm("mov.b64 {%0,%1}, %2;" : "=f"(lo), "=f"(hi) : "l"(p));
    return make_float2(lo, hi);
}
__device__ __forceinline__ float lrelu(float v) { return v > 0.f ? v : 0.2f * v; }

// ---------------------------------------------------------------------------
// x = h @ fc_W   [N,128] @ [128,64]
// ---------------------------------------------------------------------------
__global__ void k_fc(const float* __restrict__ h, const float* __restrict__ W) {
    __shared__ __align__(16) float sW[IN_ * HID_];
    __shared__ __align__(16) float sh[16 * IN_];
    int tid = threadIdx.x;
    for (int i = tid; i < IN_ * HID_; i += 256) sW[i] = W[i];
    int row0 = blockIdx.x * 16;
    for (int i = tid; i < 16 * IN_; i += 256) {
        int r = i >> 7, k = i & 127;
        sh[i] = (row0 + r < N_) ? h[(size_t)(row0 + r) * IN_ + k] : 0.f;
    }
    __syncthreads();
    int col = tid & 63;
    for (int rr = tid >> 6; rr < 16; rr += 4) {
        float acc = 0.f;
#pragma unroll
        for (int k = 0; k < IN_; k += 4) {
            float4 hv = *(const float4*)&sh[rr * IN_ + k];
            acc += hv.x * sW[k * HID_ + col] + hv.y * sW[(k + 1) * HID_ + col]
                 + hv.z * sW[(k + 2) * HID_ + col] + hv.w * sW[(k + 3) * HID_ + col];
        }
        if (row0 + rr < N_) g_x[(size_t)(row0 + rr) * HID_ + col] = acc;
    }
}

// ---------------------------------------------------------------------------
// prew for all 6 slots
// ---------------------------------------------------------------------------
__global__ void k_prew6(LP p) {
    int slot = blockIdx.x;
    int L = slot / 3, m = slot % 3;
    const float* W = p.W[L] + (size_t)m * HID_ * F_;
    const float* al = p.al[L] + m * F_;
    const float* ar = p.ar[L] + m * F_;
    int tid = threadIdx.x;
    int k = tid >> 2, h = tid & 3;
    const float* wr = W + k * F_ + h * 64;
    const float* alr = al + h * 64;
    const float* arr = ar + h * 64;
    float a = 0.f, b = 0.f;
#pragma unroll 8
    for (int d = 0; d < 64; d++) { a += wr[d] * alr[d]; b += wr[d] * arr[d]; }
    g_wtab6[slot][k * 8 + h] = a;
    g_wtab6[slot][k * 8 + 4 + h] = b;
}

// ---------------------------------------------------------------------------
// eler over 6 slots: smem-staged x, register weights, FFMA2
// ---------------------------------------------------------------------------
__global__ void __launch_bounds__(256) k_eler6() {
    __shared__ __align__(16) float sx[32][68];
    int slot = blockIdx.y;
    int tid = threadIdx.x;
    int n0 = blockIdx.x * 32;

    for (int i = tid; i < 32 * 16; i += 256) {
        int r = i >> 4, q = i & 15;
        float4 v = make_float4(0.f, 0.f, 0.f, 0.f);
        if (n0 + r < N_) v = *(const float4*)&g_x[(size_t)(n0 + r) * HID_ + q * 4];
        *(float4*)&sx[r][q * 4] = v;
    }

    int nloc = tid >> 3, op = (tid >> 1) & 3, kh = tid & 1;
    unsigned long long wreg[32];
    {
        const float* wt = g_wtab6[slot];
#pragma unroll
        for (int j = 0; j < 32; j++) {
            int k = kh * 32 + j;
            wreg[j] = *(const unsigned long long*)&wt[k * 8 + op * 2];
        }
    }
    __syncthreads();

    int n = n0 + nloc;
    unsigned long long acc = 0ull;
    const float* xr = sx[nloc] + kh * 32;
#pragma unroll
    for (int q = 0; q < 8; q++) {
        ulonglong2 xv = *(const ulonglong2*)(xr + q * 4);
        float2 xf0 = unpack2(xv.x);
        float2 xf1 = unpack2(xv.y);
        fma2(acc, packf2(xf0.x, xf0.x), wreg[q * 4 + 0]);
        fma2(acc, packf2(xf0.y, xf0.y), wreg[q * 4 + 1]);
        fma2(acc, packf2(xf1.x, xf1.x), wreg[q * 4 + 2]);
        fma2(acc, packf2(xf1.y, xf1.y), wreg[q * 4 + 3]);
    }
    float2 r = unpack2(acc);
    float plo = __shfl_xor_sync(0xffffffffu, r.x, 1);
    float phi = __shfl_xor_sync(0xffffffffu, r.y, 1);
    if (kh == 0 && n < N_) {
        float o0 = r.x + plo;
        float o1 = r.y + phi;
        if (op < 2) *(float2*)&g_el[slot * NH + n * 4 + op * 2] = make_float2(o0, o1);
        else        *(float2*)&g_er[slot * NH + n * 4 + (op - 2) * 2] = make_float2(o0, o1);
    }
}

// ---------------------------------------------------------------------------
// Batched CSR construction
// ---------------------------------------------------------------------------
__global__ void k_zerocnt4() {
    int i = blockIdx.x * 256 + threadIdx.x;
    if (i < SC4N) g_cnt4[i] = 0;
}
__global__ void k_hist4(G4 a) {
    int g = blockIdx.y;
    int i = blockIdx.x * 256 + threadIdx.x;
    if (i < a.E[g]) atomicAdd(&g_cnt4[g * N_ + a.d[g][i]], 1);
}

template <int NW>
__device__ __forceinline__ int scan_excl(int v, int tid, int* total) {
    int lane = tid & 31, w = tid >> 5;
    int x = v;
#pragma unroll
    for (int o = 1; o < 32; o <<= 1) {
        int y = __shfl_up_sync(0xffffffffu, x, o);
        if (lane >= o) x += y;
    }
    __shared__ int ws[NW];
    if (lane == 31) ws[w] = x;
    __syncthreads();
    if (w == 0) {
        int s = (lane < NW) ? ws[lane] : 0;
#pragma unroll
        for (int o = 1; o < NW; o <<= 1) {
            int y = __shfl_up_sync(0xffffffffu, s, o);
            if (lane >= o) s += y;
        }
        if (lane < NW) ws[lane] = s;
    }
    __syncthreads();
    int base = (w > 0) ? ws[w - 1] : 0;
    *total = ws[NW - 1];
    return base + x - v;
}

__global__ void k_scan1b() {
    int tid = threadIdx.x, b = blockIdx.x;
    int i = b * 256 + tid;
    int v = (i < SC4N) ? g_cnt4[i] : 0;
    int total;
    int excl = scan_excl<8>(v, tid, &total);
    if (i < SC4N) g_prefix[i] = excl;
    if (tid == 0) g_bsum[b] = total;
}
__global__ void k_scan2b() {
    int tid = threadIdx.x;
    int v = (tid < SCB4) ? g_bsum[tid] : 0;
    int total;
    int excl = scan_excl<32>(v, tid, &total);
    if (tid < SCB4) g_boff[tid] = excl;
    if (tid == 0) g_prefix[SC4N] = total;
}
__global__ void k_scan3b() {
    int i = blockIdx.x * 256 + threadIdx.x;
    if (i < SC4N) {
        int r = g_prefix[i] + g_boff[i >> 8];
        g_prefix[i] = r;
        g_cursor4[i] = r;
    }
}

// ---------------------------------------------------------------------------
// Scatter + edge-score precompute (CSR order).  Slot map per graph:
//   A: g0->0, g1->1, g2->2, g3->5;  B (g<2 only): g0->3, g1->4
// ---------------------------------------------------------------------------
__global__ void k_scatter4(G4 a) {
    int g = blockIdx.y;
    int i = blockIdx.x * 256 + threadIdx.x;
    if (i >= a.E[g]) return;
    int d = a.d[g][i];
    int s = a.s[g][i];
    int pos = atomicAdd(&g_cursor4[g * N_ + d], 1);
    g_esrcF[pos] = s;
    int slotA = (g == 3) ? 5 : g;
    {
        float4 e = *(const float4*)(g_el + slotA * NH + s * 4);
        float4 r = *(const float4*)(g_er + slotA * NH + d * 4);
        float4 v;
        v.x = lrelu(e.x + r.x); v.y = lrelu(e.y + r.y);
        v.z = lrelu(e.z + r.z); v.w = lrelu(e.w + r.w);
        g_escA[pos] = v;
    }
    if (g < 2) {
        int slotB = g + 3;
        float4 e = *(const float4*)(g_el + slotB * NH + s * 4);
        float4 r = *(const float4*)(g_er + slotB * NH + d * 4);
        float4 v;
        v.x = lrelu(e.x + r.x); v.y = lrelu(e.y + r.y);
        v.z = lrelu(e.z + r.z); v.w = lrelu(e.w + r.w);
        g_escB[pos] = v;
    }
}

// ---------------------------------------------------------------------------
// Packed gather-accumulate: per edge LDG64 + 2 LDS128 + 4 FFMA2
// ---------------------------------------------------------------------------
__device__ __forceinline__ void gather_p(const int* __restrict__ ssrc,
                                         const unsigned long long (*__restrict__ salp)[4],
                                         int cnt, int lane,
                                         unsigned long long accp[4]) {
    const float* xb = g_x;
    int i = 0;
    for (; i + 4 <= cnt; i += 4) {
        int s0 = ssrc[i], s1 = ssrc[i + 1], s2 = ssrc[i + 2], s3 = ssrc[i + 3];
        unsigned long long x0 = *(const unsigned long long*)(xb + (size_t)s0 * HID_ + lane * 2);
        unsigned long long x1 = *(const unsigned long long*)(xb + (size_t)s1 * HID_ + lane * 2);
        unsigned long long x2 = *(const unsigned long long*)(xb + (size_t)s2 * HID_ + lane * 2);
        unsigned long long x3 = *(const unsigned long long*)(xb + (size_t)s3 * HID_ + lane * 2);
        ulonglong2 pa0 = *(const ulonglong2*)&salp[i][0];
        ulonglong2 pb0 = *(const ulonglong2*)&salp[i][2];
        ulonglong2 pa1 = *(const ulonglong2*)&salp[i + 1][0];
        ulonglong2 pb1 = *(const ulonglong2*)&salp[i + 1][2];
        ulonglong2 pa2 = *(const ulonglong2*)&salp[i + 2][0];
        ulonglong2 pb2 = *(const ulonglong2*)&salp[i + 2][2];
        ulonglong2 pa3 = *(const ulonglong2*)&salp[i + 3][0];
        ulonglong2 pb3 = *(const ulonglong2*)&salp[i + 3][2];
        fma2(accp[0], pa0.x, x0); fma2(accp[1], pa0.y, x0);
        fma2(accp[2], pb0.x, x0); fma2(accp[3], pb0.y, x0);
        fma2(accp[0], pa1.x, x1); fma2(accp[1], pa1.y, x1);
        fma2(accp[2], pb1.x, x1); fma2(accp[3], pb1.y, x1);
        fma2(accp[0], pa2.x, x2); fma2(accp[1], pa2.y, x2);
        fma2(accp[2], pb2.x, x2); fma2(accp[3], pb2.y, x2);
        fma2(accp[0], pa3.x, x3); fma2(accp[1], pa3.y, x3);
        fma2(accp[2], pb3.x, x3); fma2(accp[3], pb3.y, x3);
    }
    for (; i < cnt; i++) {
        int s = ssrc[i];
        unsigned long long xv = *(const unsigned long long*)(xb + (size_t)s * HID_ + lane * 2);
        ulonglong2 pa = *(const ulonglong2*)&salp[i][0];
        ulonglong2 pb = *(const ulonglong2*)&salp[i][2];
        fma2(accp[0], pa.x, xv); fma2(accp[1], pa.y, xv);
        fma2(accp[2], pb.x, xv); fma2(accp[3], pb.y, xv);
    }
}

// ---------------------------------------------------------------------------
// GAT conv in x-space — WARP per dst node, 6 slots; coalesced escore reads.
// ---------------------------------------------------------------------------
__global__ void __launch_bounds__(256) k_conv6() {
    __shared__ int s_src[8][32];
    __shared__ __align__(16) unsigned long long s_alp[8][32][4];

    int slot = blockIdx.y;
    int gi = (slot == 5) ? 3 : (slot % 3);
    const float4* esc = (slot == 3 || slot == 4) ? g_escB : g_escA;
    float* aggb = g_agg + (size_t)slot * NF;

    int tid = threadIdx.x, lane = tid & 31, w = tid >> 5;
    int n = blockIdx.x * 8 + w;
    if (n >= N_) return;

    int e0 = g_prefix[gi * N_ + n], e1 = g_prefix[gi * N_ + n + 1];
    int deg = e1 - e0;

    unsigned long long accp[4] = {0ull, 0ull, 0ull, 0ull};

    if (deg > 0 && deg <= 32) {
        int s = -1;
        float v0 = -FLT_MAX, v1 = -FLT_MAX, v2 = -FLT_MAX, v3 = -FLT_MAX;
        if (lane < deg) {
            s = g_esrcF[e0 + lane];
            float4 v4 = esc[e0 + lane];
            v0 = v4.x; v1 = v4.y; v2 = v4.z; v3 = v4.w;
        }
        float m0 = v0, m1 = v1, m2 = v2, m3 = v3;
#pragma unroll
        for (int o = 16; o > 0; o >>= 1) {
            m0 = fmaxf(m0, __shfl_xor_sync(0xffffffffu, m0, o));
            m1 = fmaxf(m1, __shfl_xor_sync(0xffffffffu, m1, o));
            m2 = fmaxf(m2, __shfl_xor_sync(0xffffffffu, m2, o));
            m3 = fmaxf(m3, __shfl_xor_sync(0xffffffffu, m3, o));
        }
        float e0f = (lane < deg) ? __expf(v0 - m0) : 0.f;
        float e1f = (lane < deg) ? __expf(v1 - m1) : 0.f;
        float e2f = (lane < deg) ? __expf(v2 - m2) : 0.f;
        float e3f = (lane < deg) ? __expf(v3 - m3) : 0.f;
        float s0 = e0f, s1 = e1f, s2 = e2f, s3 = e3f;
#pragma unroll
        for (int o = 16; o > 0; o >>= 1) {
            s0 += __shfl_xor_sync(0xffffffffu, s0, o);
            s1 += __shfl_xor_sync(0xffffffffu, s1, o);
            s2 += __shfl_xor_sync(0xffffffffu, s2, o);
            s3 += __shfl_xor_sync(0xffffffffu, s3, o);
        }
        float a0 = e0f / s0, a1 = e1f / s1, a2 = e2f / s2, a3 = e3f / s3;
        s_src[w][lane] = s;
        s_alp[w][lane][0] = packf2(a0, a0);
        s_alp[w][lane][1] = packf2(a1, a1);
        s_alp[w][lane][2] = packf2(a2, a2);
        s_alp[w][lane][3] = packf2(a3, a3);
        __syncwarp();
        gather_p(s_src[w], s_alp[w], deg, lane, accp);
    } else if (deg > 32) {
        float mx[4] = {-FLT_MAX, -FLT_MAX, -FLT_MAX, -FLT_MAX};
        float sm[4] = {0.f, 0.f, 0.f, 0.f};
        for (int e = e0 + lane; e < e1; e += 32) {
            float4 v4 = esc[e];
            float v[4] = {v4.x, v4.y, v4.z, v4.w};
#pragma unroll
            for (int h = 0; h < 4; h++) {
                float nm = fmaxf(mx[h], v[h]);
                sm[h] = sm[h] * __expf(mx[h] - nm) + __expf(v[h] - nm);
                mx[h] = nm;
            }
        }
#pragma unroll
        for (int h = 0; h < 4; h++) {
#pragma unroll
            for (int o = 16; o > 0; o >>= 1) {
                float om = __shfl_xor_sync(0xffffffffu, mx[h], o);
                float os = __shfl_xor_sync(0xffffffffu, sm[h], o);
                float nm = fmaxf(mx[h], om);
                sm[h] = sm[h] * __expf(mx[h] - nm) + os * __expf(om - nm);
                mx[h] = nm;
            }
        }
        float inv[4];
#pragma unroll
        for (int h = 0; h < 4; h++) inv[h] = 1.f / sm[h];

        for (int base = 0; base < deg; base += 32) {
            int cnt = min(32, deg - base);
            int s = -1;
            float a0 = 0.f, a1 = 0.f, a2 = 0.f, a3 = 0.f;
            if (lane < cnt) {
                s = g_esrcF[e0 + base + lane];
                float4 v4 = esc[e0 + base + lane];
                a0 = __expf(v4.x - mx[0]) * inv[0];
                a1 = __expf(v4.y - mx[1]) * inv[1];
                a2 = __expf(v4.z - mx[2]) * inv[2];
                a3 = __expf(v4.w - mx[3]) * inv[3];
            }
            __syncwarp();
            s_src[w][lane] = s;
            s_alp[w][lane][0] = packf2(a0, a0);
            s_alp[w][lane][1] = packf2(a1, a1);
            s_alp[w][lane][2] = packf2(a2, a2);
            s_alp[w][lane][3] = packf2(a3, a3);
            __syncwarp();
            gather_p(s_src[w], s_alp[w], cnt, lane, accp);
        }
    }

    float2 r0 = unpack2(accp[0]);
    float2 r1 = unpack2(accp[1]);
    float2 r2 = unpack2(accp[2]);
    float2 r3 = unpack2(accp[3]);
    float4* op = (float4*)(aggb + (size_t)n * F_ + (lane * 2) * 4);
    op[0] = make_float4(r0.x, r1.x, r2.x, r3.x);
    op[1] = make_float4(r0.y, r1.y, r2.y, r3.y);
}

// ---------------------------------------------------------------------------
// Post-GEMM with packed f32x2 FMA over k-pairs, batched over 6 slots (y)
// ---------------------------------------------------------------------------
__global__ void __launch_bounds__(256) k_post6(LP p) {
    __shared__ float sagg[32 * 272];
    int slot = blockIdx.y;
    int L = slot / 3, m = slot % 3;
    const float* W = p.W[L] + (size_t)m * HID_ * F_;
    const float* bias = p.bb[L] + m * F_;
    const float* aggb = g_agg + (size_t)slot * NF;

    int tid = threadIdx.x;
    int h = tid >> 6, d = tid & 63;
    unsigned long long wp[HID_ / 2];
#pragma unroll
    for (int q = 0; q < HID_ / 2; q++)
        wp[q] = packf2(W[(2 * q) * F_ + h * 64 + d], W[(2 * q + 1) * F_ + h * 64 + d]);
    float bv = bias[tid];
    int n0 = blockIdx.x * 32;
    for (int idx = tid; idx < 32 * 256; idx += 256) {
        int r = idx >> 8, j = idx & 255;
        int kk = j >> 2, hh = j & 3;
        float v = (n0 + r < N_) ? aggb[(size_t)(n0 + r) * F_ + j] : 0.f;
        sagg[r * 272 + hh * 68 + kk] = v;
    }
    __syncthreads();
    int rmax = min(32, N_ - n0);
    for (int r = 0; r < rmax; r++) {
        const ulonglong2* ap = (const ulonglong2*)(sagg + r * 272 + h * 68);
        unsigned long long acc = 0ull;
#pragma unroll
        for (int q = 0; q < 16; q++) {
            ulonglong2 av = ap[q];
            fma2(acc, av.x, wp[2 * q]);
            fma2(acc, av.y, wp[2 * q + 1]);
        }
        float o = unpack_sum(acc) + bv;
        g_emb[(size_t)slot * NF + (size_t)(n0 + r) * F_ + tid] = o > 0.f ? o : expm1f(o);
    }
}

// ---------------------------------------------------------------------------
// W1 prep: bf16x2-pack all 3 W1 matrices (y = slot); zeros wsum[slot]
// ---------------------------------------------------------------------------
__global__ void k_prepW1b3(const float* __restrict__ W1a,
                           const float* __restrict__ W1b,
                           const float* __restrict__ W1f) {
    int z = blockIdx.y;
    const float* W1 = (z == 0) ? W1a : (z == 1) ? W1b : W1f;
    int j = blockIdx.x * 256 + threadIdx.x;
    if (j < W1HALF) {
        int pp = j >> 7, c = j & 127;
        g_W1bf[z * W1HALF + j] = pack_bf2(W1[(2 * pp) * SAH_ + c], W1[(2 * pp + 1) * SAH_ + c]);
    }
    if (blockIdx.x == 0 && threadIdx.x < 4) g_wsum[z][threadIdx.x] = 0.f;
}

// ---------------------------------------------------------------------------
// Semantic-attention score GEMM, bf16; batched over stages via blockIdx.z
// ---------------------------------------------------------------------------
__global__ void __launch_bounds__(256) k_wscore_tc(int sel, LP p,
                                                   const float* __restrict__ b1f,
                                                   const float* __restrict__ w2f) {
    __shared__ unsigned int sA[128 * 18];
    __shared__ unsigned int sB[128 * 18];
    __shared__ float s_b1[SAH_], s_w2[SAH_];
    __shared__ float sred[8];

    int tid = threadIdx.x, lane = tid & 31, w = tid >> 5;
    int m = blockIdx.y;
    int z = blockIdx.z;
    int stage = sel ? 2 : z;
    int n0 = blockIdx.x * 128;
    const float* Z = sel ? (g_hl + (size_t)m * NF)
                         : (g_emb + (size_t)(z * 3 + m) * NF);
    const unsigned int* W1p = g_W1bf + (sel ? 2 : z) * W1HALF;
    const float* b1 = sel ? b1f : p.b1[z];
    const float* w2 = sel ? w2f : p.w2[z];
    if (tid < SAH_) { s_b1[tid] = b1[tid]; s_w2[tid] = w2[tid]; }

    float acc[16][4];
#pragma unroll
    for (int t = 0; t < 16; t++)
#pragma unroll
        for (int j = 0; j < 4; j++) acc[t][j] = 0.f;

    int g4 = lane >> 2, tg = lane & 3;
    int ar0 = w * 16 + g4, ar1 = ar0 + 8;

    for (int f0 = 0; f0 < F_; f0 += 32) {
        int p0 = f0 >> 1;
        __syncthreads();
        for (int i = tid; i < 128 * 16; i += 256) {
            int r = i >> 4, pp = i & 15;
            int n = n0 + r;
            float2 v = make_float2(0.f, 0.f);
            if (n < N_) v = *(const float2*)&Z[(size_t)n * F_ + f0 + pp * 2];
            sA[r * 18 + pp] = pack_bf2(v.x, v.y);
        }
        for (int i = tid; i < 128 * 16; i += 256) {
            int c = i & 127, pp = i >> 7;
            sB[c * 18 + pp] = W1p[(p0 + pp) * 128 + c];
        }
        __syncthreads();
#pragma unroll
        for (int s = 0; s < 2; s++) {
            int base = s * 8;
            unsigned int a0 = sA[ar0 * 18 + base + tg];
            unsigned int a1 = sA[ar1 * 18 + base + tg];
            unsigned int a2 = sA[ar0 * 18 + base + tg + 4];
            unsigned int a3 = sA[ar1 * 18 + base + tg + 4];
#pragma unroll
            for (int t = 0; t < 16; t++) {
                int c = t * 8 + g4;
                unsigned int b0 = sB[c * 18 + base + tg];
                unsigned int b1v = sB[c * 18 + base + tg + 4];
                mma_bf16(acc[t][0], acc[t][1], acc[t][2], acc[t][3],
                         a0, a1, a2, a3, b0, b1v);
            }
        }
    }

    float tot = 0.f;
    bool v0 = (n0 + ar0) < N_, v1 = (n0 + ar1) < N_;
#pragma unroll
    for (int t = 0; t < 16; t++) {
        int c0 = t * 8 + tg * 2, c1 = c0 + 1;
        float bb0 = s_b1[c0], bb1 = s_b1[c1];
        float ww0 = s_w2[c0], ww1 = s_w2[c1];
        if (v0) tot += tanh_fast(acc[t][0] + bb0) * ww0 + tanh_fast(acc[t][1] + bb1) * ww1;
        if (v1) tot += tanh_fast(acc[t][2] + bb0) * ww0 + tanh_fast(acc[t][3] + bb1) * ww1;
    }
#pragma unroll
    for (int o = 16; o > 0; o >>= 1) tot += __shfl_xor_sync(0xffffffffu, tot, o);
    if (lane == 0) sred[w] = tot;
    __syncthreads();
    if (tid == 0) {
        float s = 0.f;
#pragma unroll
        for (int i = 0; i < 8; i++) s += sred[i];
        atomicAdd(&g_wsum[stage][m], s);
    }
}

__global__ void k_beta2() {
    if (threadIdx.x < 2) {
        int stage = threadIdx.x;
        float w[3];
        float mx = -1e30f;
        for (int m = 0; m < 3; m++) { w[m] = g_wsum[stage][m] / (float)N_; mx = fmaxf(mx, w[m]); }
        float s = 0.f;
        for (int m = 0; m < 3; m++) { w[m] = __expf(w[m] - mx); s += w[m]; }
        for (int m = 0; m < 3; m++) g_beta[stage][m] = w[m] / s;
    }
}
__global__ void k_betaF() {
    if (threadIdx.x == 0) {
        float w[2];
        float mx = -1e30f;
        for (int m = 0; m < 2; m++) { w[m] = g_wsum[2][m] / (float)N_; mx = fmaxf(mx, w[m]); }
        float s = 0.f;
        for (int m = 0; m < 2; m++) { w[m] = __expf(w[m] - mx); s += w[m]; }
        for (int m = 0; m < 2; m++) g_beta[2][m] = w[m] / s;
    }
}

__global__ void k_combine01() {
    int stage = blockIdx.y;
    size_t i = ((size_t)blockIdx.x * 256 + threadIdx.x) * 4;
    if (i >= NF) return;
    const float* base = g_emb + (size_t)stage * 3 * NF;
    float b0 = g_beta[stage][0], b1 = g_beta[stage][1], b2 = g_beta[stage][2];
    float4 v0 = *(const float4*)&base[i];
    float4 v1 = *(const float4*)&base[NF + i];
    float4 v2 = *(const float4*)&base[2 * NF + i];
    float4 r;
    r.x = b0 * v0.x + b1 * v1.x + b2 * v2.x;
    r.y = b0 * v0.y + b1 * v1.y + b2 * v2.y;
    r.z = b0 * v0.z + b1 * v1.z + b2 * v2.z;
    r.w = b0 * v0.w + b1 * v1.w + b2 * v2.w;
    *(float4*)&g_hl[stage * NF + i] = r;
}

// ---------------------------------------------------------------------------
// Fused final combine + prediction
// ---------------------------------------------------------------------------
__global__ void __launch_bounds__(256) k_predF(const float* __restrict__ W,
                                               const float* __restrict__ b,
                                               float* __restrict__ out,
                                               float* __restrict__ dup) {
    __shared__ float sW[F_ * OUT_];
    __shared__ __align__(16) float sr[16 * F_];
    int tid = threadIdx.x;
    for (int i = tid; i < F_ * OUT_; i += 256) sW[i] = W[i];
    float b0 = g_beta[2][0], b1 = g_beta[2][1];
    int n0 = blockIdx.x * 16;
    for (int i = tid; i < 16 * F_ / 4; i += 256) {
        int r = (i * 4) >> 8, f = (i * 4) & 255;
        int n = n0 + r;
        float4 rv = make_float4(0.f, 0.f, 0.f, 0.f);
        if (n < N_) {
            float4 v0 = *(const float4*)&g_hl[(size_t)n * F_ + f];
            float4 v1 = *(const float4*)&g_hl[NF + (size_t)n * F_ + f];
            rv.x = b0 * v0.x + b1 * v1.x;
            rv.y = b0 * v0.y + b1 * v1.y;
            rv.z = b0 * v0.z + b1 * v1.z;
            rv.w = b0 * v0.w + b1 * v1.w;
            if (dup) *(float4*)&dup[(size_t)n * F_ + f] = rv;
        }
        *(float4*)&sr[r * F_ + f] = rv;
    }
    __syncthreads();
    int node = n0 + (tid >> 4);
    int o = tid & 15;
    if (node >= N_) return;
    const float* hr = sr + (tid >> 4) * F_;
    float acc = b[o];
#pragma unroll 8
    for (int f = 0; f < F_; f++) acc += hr[f] * sW[f * OUT_ + o];
    out[(size_t)node * OUT_ + o] = acc;
}

// ---------------------------------------------------------------------------
// Host launcher — single stream, graph-capturable
// ---------------------------------------------------------------------------
extern "C" void kernel_launch(void* const* d_in, const int* in_sizes, int n_in,
                              void* d_out, int out_size) {
    const float* h = (const float*)d_in[0];
    G4 a;
    a.s[0] = (const int*)d_in[1]; a.d[0] = (const int*)d_in[2];
    a.s[1] = (const int*)d_in[3]; a.d[1] = (const int*)d_in[4];
    a.s[2] = (const int*)d_in[5]; a.d[2] = (const int*)d_in[6];
    a.s[3] = (const int*)d_in[7]; a.d[3] = (const int*)d_in[8];
    a.E[0] = in_sizes[1]; a.E[1] = in_sizes[3]; a.E[2] = in_sizes[5]; a.E[3] = in_sizes[7];
    const float* fcW = (const float*)d_in[10];
    LP p;
    p.W[0]  = (const float*)d_in[11]; p.W[1]  = (const float*)d_in[18];
    p.al[0] = (const float*)d_in[12]; p.al[1] = (const float*)d_in[19];
    p.ar[0] = (const float*)d_in[13]; p.ar[1] = (const float*)d_in[20];
    p.bb[0] = (const float*)d_in[14]; p.bb[1] = (const float*)d_in[21];
    const float* saW1[2] = {(const float*)d_in[15], (const float*)d_in[22]};
    p.b1[0] = (const float*)d_in[16]; p.b1[1] = (const float*)d_in[23];
    p.w2[0] = (const float*)d_in[17]; p.w2[1] = (const float*)d_in[24];
    const float* saW1f = (const float*)d_in[25];
    const float* sab1f = (const float*)d_in[26];
    const float* saw2f = (const float*)d_in[27];
    const float* predW = (const float*)d_in[28];
    const float* predb = (const float*)d_in[29];
    float* out = (float*)d_out;

    int maxE = a.E[0];
    for (int g = 1; g < 4; g++) if (a.E[g] > maxE) maxE = a.E[g];
    const int CMB = (int)((NF / 4 + 255) / 256);

    k_fc<<<(N_ + 15) / 16, 256>>>(h, fcW);
    k_prew6<<<6, 256>>>(p);
    k_zerocnt4<<<SCB4, 256>>>();
    k_hist4<<<dim3((maxE + 255) / 256, 4), 256>>>(a);
    k_eler6<<<dim3((N_ + 31) / 32, 6), 256>>>();
    k_scan1b<<<SCB4, 256>>>();
    k_scan2b<<<1, 1024>>>();
    k_scan3b<<<SCB4, 256>>>();
    k_scatter4<<<dim3((maxE + 255) / 256, 4), 256>>>(a);

    k_conv6<<<dim3((N_ + 7) / 8, 6), 256>>>();
    k_post6<<<dim3((N_ + 31) / 32, 6), 256>>>(p);

    k_prepW1b3<<<dim3((W1HALF + 255) / 256, 3), 256>>>(saW1[0], saW1[1], saW1f);
    k_wscore_tc<<<dim3(WSB_N, 3, 2), 256>>>(0, p, nullptr, nullptr);
    k_beta2<<<1, 32>>>();
    k_combine01<<<dim3(CMB, 2), 256>>>();

    k_wscore_tc<<<dim3(WSB_N, 2, 1), 256>>>(1, p, sab1f, saw2f);
    k_betaF<<<1, 32>>>();
    float* dup = (out_size >= N_ * (OUT_ + F_)) ? out + (size_t)N_ * OUT_ : nullptr;
    k_predF<<<(N_ + 15) / 16, 256>>>(predW, predb, out, dup);
}

// round 17
// speedup vs baseline: 1.0273x; 1.0273x over previous
#include <cuda_runtime.h>
#include <math.h>
#include <float.h>

// ---------------------------------------------------------------------------
// Problem constants
// ---------------------------------------------------------------------------
constexpr int N_   = 50000;
constexpr int IN_  = 128;
constexpr int HID_ = 64;
constexpr int H_   = 4;
constexpr int F_   = 256;    // H*D
constexpr int OUT_ = 16;
constexpr int SAH_ = 128;
constexpr int EMAX_ = 800000;

constexpr size_t NF = (size_t)N_ * F_;
constexpr int NH = N_ * H_;
constexpr int SC4N = 4 * N_;
constexpr int SCB4 = (SC4N + 255) / 256;
constexpr int WSB_N = (N_ + 127) / 128;
constexpr int W1HALF = (SAH_ * F_) / 2;

// ---------------------------------------------------------------------------
// Device scratch
// ---------------------------------------------------------------------------
__device__ float g_x[(size_t)N_ * HID_];
__device__ __align__(16) float g_el[6 * NH];
__device__ __align__(16) float g_er[6 * NH];
__device__ __align__(16) float g_wtab6[6][HID_ * 8];
__device__ float g_agg[6 * NF];
__device__ float g_emb[6 * NF];
__device__ float g_hl[2 * NF];
__device__ float g_wsum[3][4];
__device__ float g_beta[3][4];
__device__ unsigned int g_W1bf[3 * W1HALF];        // 3 W1 slots (L0, L1, final)

// Batched CSR scratch
__device__ int g_cnt4[SC4N];
__device__ int g_cursor4[SC4N];
__device__ int g_prefix[SC4N + 1];
__device__ int g_esrcF[4 * EMAX_];
__device__ int g_bsum[SCB4];
__device__ int g_boff[SCB4];

struct G4 { const int* s[4]; const int* d[4]; int E[4]; };
struct LP {
    const float* W[2];
    const float* al[2];
    const float* ar[2];
    const float* bb[2];
    const float* b1[2];
    const float* w2[2];
};

// ---------------------------------------------------------------------------
// Low-level helpers
// ---------------------------------------------------------------------------
__device__ __forceinline__ unsigned int pack_bf2(float lo, float hi) {
    unsigned int r;
    asm("cvt.rn.bf16x2.f32 %0, %1, %2;" : "=r"(r) : "f"(hi), "f"(lo));
    return r;
}
__device__ __forceinline__ float tanh_fast(float x) {
    float r;
    asm("tanh.approx.f32 %0, %1;" : "=f"(r) : "f"(x));
    return r;
}
__device__ __forceinline__ void mma_bf16(float& d0, float& d1, float& d2, float& d3,
                                         unsigned int a0, unsigned int a1,
                                         unsigned int a2, unsigned int a3,
                                         unsigned int b0, unsigned int b1) {
    asm("mma.sync.aligned.m16n8k16.row.col.f32.bf16.bf16.f32 "
        "{%0,%1,%2,%3}, {%4,%5,%6,%7}, {%8,%9}, {%0,%1,%2,%3};"
        : "+f"(d0), "+f"(d1), "+f"(d2), "+f"(d3)
        : "r"(a0), "r"(a1), "r"(a2), "r"(a3), "r"(b0), "r"(b1));
}
__device__ __forceinline__ void fma2(unsigned long long& acc,
                                     unsigned long long a, unsigned long long b) {
    asm("fma.rn.f32x2 %0, %1, %2, %0;" : "+l"(acc) : "l"(a), "l"(b));
}
__device__ __forceinline__ unsigned long long packf2(float lo, float hi) {
    unsigned long long r;
    asm("mov.b64 %0, {%1,%2};" : "=l"(r) : "f"(lo), "f"(hi));
    return r;
}
__device__ __forceinline__ float unpack_sum(unsigned long long p) {
    float lo, hi;
    asm("mov.b64 {%0,%1}, %2;" : "=f"(lo), "=f"(hi) : "l"(p));
    return lo + hi;
}
__device__ __forceinline__ float2 unpack2(unsigned long long p) {
    float lo, hi;
    asm("mov.b64 {%0,%1}, %2;" : "=f"(lo), "=f"(hi) : "l"(p));
    return make_float2(lo, hi);
}

// ---------------------------------------------------------------------------
// x = h @ fc_W   [N,128] @ [128,64]
// ---------------------------------------------------------------------------
__global__ void k_fc(const float* __restrict__ h, const float* __restrict__ W) {
    __shared__ __align__(16) float sW[IN_ * HID_];
    __shared__ __align__(16) float sh[16 * IN_];
    int tid = threadIdx.x;
    for (int i = tid; i < IN_ * HID_; i += 256) sW[i] = W[i];
    int row0 = blockIdx.x * 16;
    for (int i = tid; i < 16 * IN_; i += 256) {
        int r = i >> 7, k = i & 127;
        sh[i] = (row0 + r < N_) ? h[(size_t)(row0 + r) * IN_ + k] : 0.f;
    }
    __syncthreads();
    int col = tid & 63;
    for (int rr = tid >> 6; rr < 16; rr += 4) {
        float acc = 0.f;
#pragma unroll
        for (int k = 0; k < IN_; k += 4) {
            float4 hv = *(const float4*)&sh[rr * IN_ + k];
            acc += hv.x * sW[k * HID_ + col] + hv.y * sW[(k + 1) * HID_ + col]
                 + hv.z * sW[(k + 2) * HID_ + col] + hv.w * sW[(k + 3) * HID_ + col];
        }
        if (row0 + rr < N_) g_x[(size_t)(row0 + rr) * HID_ + col] = acc;
    }
}

// ---------------------------------------------------------------------------
// prew for all 6 slots
// ---------------------------------------------------------------------------
__global__ void k_prew6(LP p) {
    int slot = blockIdx.x;
    int L = slot / 3, m = slot % 3;
    const float* W = p.W[L] + (size_t)m * HID_ * F_;
    const float* al = p.al[L] + m * F_;
    const float* ar = p.ar[L] + m * F_;
    int tid = threadIdx.x;
    int k = tid >> 2, h = tid & 3;
    const float* wr = W + k * F_ + h * 64;
    const float* alr = al + h * 64;
    const float* arr = ar + h * 64;
    float a = 0.f, b = 0.f;
#pragma unroll 8
    for (int d = 0; d < 64; d++) { a += wr[d] * alr[d]; b += wr[d] * arr[d]; }
    g_wtab6[slot][k * 8 + h] = a;
    g_wtab6[slot][k * 8 + 4 + h] = b;
}

// ---------------------------------------------------------------------------
// eler over 6 slots: smem-staged x, register weights, FFMA2
// ---------------------------------------------------------------------------
__global__ void __launch_bounds__(256) k_eler6() {
    __shared__ __align__(16) float sx[32][68];
    int slot = blockIdx.y;
    int tid = threadIdx.x;
    int n0 = blockIdx.x * 32;

    for (int i = tid; i < 32 * 16; i += 256) {
        int r = i >> 4, q = i & 15;
        float4 v = make_float4(0.f, 0.f, 0.f, 0.f);
        if (n0 + r < N_) v = *(const float4*)&g_x[(size_t)(n0 + r) * HID_ + q * 4];
        *(float4*)&sx[r][q * 4] = v;
    }

    int nloc = tid >> 3, op = (tid >> 1) & 3, kh = tid & 1;
    unsigned long long wreg[32];
    {
        const float* wt = g_wtab6[slot];
#pragma unroll
        for (int j = 0; j < 32; j++) {
            int k = kh * 32 + j;
            wreg[j] = *(const unsigned long long*)&wt[k * 8 + op * 2];
        }
    }
    __syncthreads();

    int n = n0 + nloc;
    unsigned long long acc = 0ull;
    const float* xr = sx[nloc] + kh * 32;
#pragma unroll
    for (int q = 0; q < 8; q++) {
        ulonglong2 xv = *(const ulonglong2*)(xr + q * 4);
        float2 xf0 = unpack2(xv.x);
        float2 xf1 = unpack2(xv.y);
        fma2(acc, packf2(xf0.x, xf0.x), wreg[q * 4 + 0]);
        fma2(acc, packf2(xf0.y, xf0.y), wreg[q * 4 + 1]);
        fma2(acc, packf2(xf1.x, xf1.x), wreg[q * 4 + 2]);
        fma2(acc, packf2(xf1.y, xf1.y), wreg[q * 4 + 3]);
    }
    float2 r = unpack2(acc);
    float plo = __shfl_xor_sync(0xffffffffu, r.x, 1);
    float phi = __shfl_xor_sync(0xffffffffu, r.y, 1);
    if (kh == 0 && n < N_) {
        float o0 = r.x + plo;
        float o1 = r.y + phi;
        if (op < 2) *(float2*)&g_el[slot * NH + n * 4 + op * 2] = make_float2(o0, o1);
        else        *(float2*)&g_er[slot * NH + n * 4 + (op - 2) * 2] = make_float2(o0, o1);
    }
}

// ---------------------------------------------------------------------------
// Batched CSR construction
// ---------------------------------------------------------------------------
__global__ void k_zerocnt4() {
    int i = blockIdx.x * 256 + threadIdx.x;
    if (i < SC4N) g_cnt4[i] = 0;
}
__global__ void k_hist4(G4 a) {
    int g = blockIdx.y;
    int i = blockIdx.x * 256 + threadIdx.x;
    if (i < a.E[g]) atomicAdd(&g_cnt4[g * N_ + a.d[g][i]], 1);
}

template <int NW>
__device__ __forceinline__ int scan_excl(int v, int tid, int* total) {
    int lane = tid & 31, w = tid >> 5;
    int x = v;
#pragma unroll
    for (int o = 1; o < 32; o <<= 1) {
        int y = __shfl_up_sync(0xffffffffu, x, o);
        if (lane >= o) x += y;
    }
    __shared__ int ws[NW];
    if (lane == 31) ws[w] = x;
    __syncthreads();
    if (w == 0) {
        int s = (lane < NW) ? ws[lane] : 0;
#pragma unroll
        for (int o = 1; o < NW; o <<= 1) {
            int y = __shfl_up_sync(0xffffffffu, s, o);
            if (lane >= o) s += y;
        }
        if (lane < NW) ws[lane] = s;
    }
    __syncthreads();
    int base = (w > 0) ? ws[w - 1] : 0;
    *total = ws[NW - 1];
    return base + x - v;
}

__global__ void k_scan1b() {
    int tid = threadIdx.x, b = blockIdx.x;
    int i = b * 256 + tid;
    int v = (i < SC4N) ? g_cnt4[i] : 0;
    int total;
    int excl = scan_excl<8>(v, tid, &total);
    if (i < SC4N) g_prefix[i] = excl;
    if (tid == 0) g_bsum[b] = total;
}
__global__ void k_scan2b() {
    int tid = threadIdx.x;
    int v = (tid < SCB4) ? g_bsum[tid] : 0;
    int total;
    int excl = scan_excl<32>(v, tid, &total);
    if (tid < SCB4) g_boff[tid] = excl;
    if (tid == 0) g_prefix[SC4N] = total;
}
__global__ void k_scan3b() {
    int i = blockIdx.x * 256 + threadIdx.x;
    if (i < SC4N) {
        int r = g_prefix[i] + g_boff[i >> 8];
        g_prefix[i] = r;
        g_cursor4[i] = r;
    }
}
__global__ void k_scatter4(G4 a) {
    int g = blockIdx.y;
    int i = blockIdx.x * 256 + threadIdx.x;
    if (i >= a.E[g]) return;
    int d = a.d[g][i];
    int pos = atomicAdd(&g_cursor4[g * N_ + d], 1);
    g_esrcF[pos] = a.s[g][i];
}

// ---------------------------------------------------------------------------
// Packed gather-accumulate: per edge LDG64 + 2 LDS128 + 4 FFMA2
// ---------------------------------------------------------------------------
__device__ __forceinline__ void gather_p(const int* __restrict__ ssrc,
                                         const unsigned long long (*__restrict__ salp)[4],
                                         int cnt, int lane,
                                         unsigned long long accp[4]) {
    const float* xb = g_x;
    int i = 0;
    for (; i + 4 <= cnt; i += 4) {
        int s0 = ssrc[i], s1 = ssrc[i + 1], s2 = ssrc[i + 2], s3 = ssrc[i + 3];
        unsigned long long x0 = *(const unsigned long long*)(xb + (size_t)s0 * HID_ + lane * 2);
        unsigned long long x1 = *(const unsigned long long*)(xb + (size_t)s1 * HID_ + lane * 2);
        unsigned long long x2 = *(const unsigned long long*)(xb + (size_t)s2 * HID_ + lane * 2);
        unsigned long long x3 = *(const unsigned long long*)(xb + (size_t)s3 * HID_ + lane * 2);
        ulonglong2 pa0 = *(const ulonglong2*)&salp[i][0];
        ulonglong2 pb0 = *(const ulonglong2*)&salp[i][2];
        ulonglong2 pa1 = *(const ulonglong2*)&salp[i + 1][0];
        ulonglong2 pb1 = *(const ulonglong2*)&salp[i + 1][2];
        ulonglong2 pa2 = *(const ulonglong2*)&salp[i + 2][0];
        ulonglong2 pb2 = *(const ulonglong2*)&salp[i + 2][2];
        ulonglong2 pa3 = *(const ulonglong2*)&salp[i + 3][0];
        ulonglong2 pb3 = *(const ulonglong2*)&salp[i + 3][2];
        fma2(accp[0], pa0.x, x0); fma2(accp[1], pa0.y, x0);
        fma2(accp[2], pb0.x, x0); fma2(accp[3], pb0.y, x0);
        fma2(accp[0], pa1.x, x1); fma2(accp[1], pa1.y, x1);
        fma2(accp[2], pb1.x, x1); fma2(accp[3], pb1.y, x1);
        fma2(accp[0], pa2.x, x2); fma2(accp[1], pa2.y, x2);
        fma2(accp[2], pb2.x, x2); fma2(accp[3], pb2.y, x2);
        fma2(accp[0], pa3.x, x3); fma2(accp[1], pa3.y, x3);
        fma2(accp[2], pb3.x, x3); fma2(accp[3], pb3.y, x3);
    }
    for (; i < cnt; i++) {
        int s = ssrc[i];
        unsigned long long xv = *(const unsigned long long*)(xb + (size_t)s * HID_ + lane * 2);
        ulonglong2 pa = *(const ulonglong2*)&salp[i][0];
        ulonglong2 pb = *(const ulonglong2*)&salp[i][2];
        fma2(accp[0], pa.x, xv); fma2(accp[1], pa.y, xv);
        fma2(accp[2], pb.x, xv); fma2(accp[3], pb.y, xv);
    }
}

// ---------------------------------------------------------------------------
// GAT conv in x-space — WARP per dst node, batched over 6 slots (y = slot)
// ---------------------------------------------------------------------------
__global__ void __launch_bounds__(256) k_conv6() {
    __shared__ int s_src[8][32];
    __shared__ __align__(16) unsigned long long s_alp[8][32][4];

    int slot = blockIdx.y;
    int gi = (slot == 5) ? 3 : (slot % 3);
    const float* elb = g_el + slot * NH;
    const float* erb = g_er + slot * NH;
    float* aggb = g_agg + (size_t)slot * NF;

    int tid = threadIdx.x, lane = tid & 31, w = tid >> 5;
    int n = blockIdx.x * 8 + w;
    if (n >= N_) return;

    int e0 = g_prefix[gi * N_ + n], e1 = g_prefix[gi * N_ + n + 1];
    int deg = e1 - e0;

    float4 ern = *(const float4*)(erb + n * 4);
    unsigned long long accp[4] = {0ull, 0ull, 0ull, 0ull};

    if (deg > 0 && deg <= 32) {
        int s = -1;
        float v0 = -FLT_MAX, v1 = -FLT_MAX, v2 = -FLT_MAX, v3 = -FLT_MAX;
        if (lane < deg) {
            s = g_esrcF[e0 + lane];
            float4 els = *(const float4*)(elb + s * 4);
            v0 = els.x + ern.x; v0 = v0 > 0.f ? v0 : 0.2f * v0;
            v1 = els.y + ern.y; v1 = v1 > 0.f ? v1 : 0.2f * v1;
            v2 = els.z + ern.z; v2 = v2 > 0.f ? v2 : 0.2f * v2;
            v3 = els.w + ern.w; v3 = v3 > 0.f ? v3 : 0.2f * v3;
        }
        float m0 = v0, m1 = v1, m2 = v2, m3 = v3;
#pragma unroll
        for (int o = 16; o > 0; o >>= 1) {
            m0 = fmaxf(m0, __shfl_xor_sync(0xffffffffu, m0, o));
            m1 = fmaxf(m1, __shfl_xor_sync(0xffffffffu, m1, o));
            m2 = fmaxf(m2, __shfl_xor_sync(0xffffffffu, m2, o));
            m3 = fmaxf(m3, __shfl_xor_sync(0xffffffffu, m3, o));
        }
        float e0f = (lane < deg) ? __expf(v0 - m0) : 0.f;
        float e1f = (lane < deg) ? __expf(v1 - m1) : 0.f;
        float e2f = (lane < deg) ? __expf(v2 - m2) : 0.f;
        float e3f = (lane < deg) ? __expf(v3 - m3) : 0.f;
        float s0 = e0f, s1 = e1f, s2 = e2f, s3 = e3f;
#pragma unroll
        for (int o = 16; o > 0; o >>= 1) {
            s0 += __shfl_xor_sync(0xffffffffu, s0, o);
            s1 += __shfl_xor_sync(0xffffffffu, s1, o);
            s2 += __shfl_xor_sync(0xffffffffu, s2, o);
            s3 += __shfl_xor_sync(0xffffffffu, s3, o);
        }
        float a0 = e0f / s0, a1 = e1f / s1, a2 = e2f / s2, a3 = e3f / s3;
        s_src[w][lane] = s;
        s_alp[w][lane][0] = packf2(a0, a0);
        s_alp[w][lane][1] = packf2(a1, a1);
        s_alp[w][lane][2] = packf2(a2, a2);
        s_alp[w][lane][3] = packf2(a3, a3);
        __syncwarp();
        gather_p(s_src[w], s_alp[w], deg, lane, accp);
    } else if (deg > 32) {
        float mx[4] = {-FLT_MAX, -FLT_MAX, -FLT_MAX, -FLT_MAX};
        float sm[4] = {0.f, 0.f, 0.f, 0.f};
        for (int e = e0 + lane; e < e1; e += 32) {
            int s = g_esrcF[e];
            float4 els = *(const float4*)(elb + s * 4);
            float v[4];
            v[0] = els.x + ern.x; v[1] = els.y + ern.y;
            v[2] = els.z + ern.z; v[3] = els.w + ern.w;
#pragma unroll
            for (int h = 0; h < 4; h++) {
                float vv = v[h] > 0.f ? v[h] : 0.2f * v[h];
                float nm = fmaxf(mx[h], vv);
                sm[h] = sm[h] * __expf(mx[h] - nm) + __expf(vv - nm);
                mx[h] = nm;
            }
        }
#pragma unroll
        for (int h = 0; h < 4; h++) {
#pragma unroll
            for (int o = 16; o > 0; o >>= 1) {
                float om = __shfl_xor_sync(0xffffffffu, mx[h], o);
                float os = __shfl_xor_sync(0xffffffffu, sm[h], o);
                float nm = fmaxf(mx[h], om);
                sm[h] = sm[h] * __expf(mx[h] - nm) + os * __expf(om - nm);
                mx[h] = nm;
            }
        }
        float inv[4];
#pragma unroll
        for (int h = 0; h < 4; h++) inv[h] = 1.f / sm[h];

        for (int base = 0; base < deg; base += 32) {
            int cnt = min(32, deg - base);
            int s = -1;
            float a0 = 0.f, a1 = 0.f, a2 = 0.f, a3 = 0.f;
            if (lane < cnt) {
                s = g_esrcF[e0 + base + lane];
                float4 els = *(const float4*)(elb + s * 4);
                float v0 = els.x + ern.x; v0 = v0 > 0.f ? v0 : 0.2f * v0;
                float v1 = els.y + ern.y; v1 = v1 > 0.f ? v1 : 0.2f * v1;
                float v2 = els.z + ern.z; v2 = v2 > 0.f ? v2 : 0.2f * v2;
                float v3 = els.w + ern.w; v3 = v3 > 0.f ? v3 : 0.2f * v3;
                a0 = __expf(v0 - mx[0]) * inv[0];
                a1 = __expf(v1 - mx[1]) * inv[1];
                a2 = __expf(v2 - mx[2]) * inv[2];
                a3 = __expf(v3 - mx[3]) * inv[3];
            }
            __syncwarp();
            s_src[w][lane] = s;
            s_alp[w][lane][0] = packf2(a0, a0);
            s_alp[w][lane][1] = packf2(a1, a1);
            s_alp[w][lane][2] = packf2(a2, a2);
            s_alp[w][lane][3] = packf2(a3, a3);
            __syncwarp();
            gather_p(s_src[w], s_alp[w], cnt, lane, accp);
        }
    }

    float2 r0 = unpack2(accp[0]);
    float2 r1 = unpack2(accp[1]);
    float2 r2 = unpack2(accp[2]);
    float2 r3 = unpack2(accp[3]);
    float4* op = (float4*)(aggb + (size_t)n * F_ + (lane * 2) * 4);
    op[0] = make_float4(r0.x, r1.x, r2.x, r3.x);
    op[1] = make_float4(r0.y, r1.y, r2.y, r3.y);
}

// ---------------------------------------------------------------------------
// Post-GEMM with packed f32x2 FMA over k-pairs, batched over 6 slots (y)
// ---------------------------------------------------------------------------
__global__ void __launch_bounds__(256) k_post6(LP p) {
    __shared__ float sagg[32 * 272];
    int slot = blockIdx.y;
    int L = slot / 3, m = slot % 3;
    const float* W = p.W[L] + (size_t)m * HID_ * F_;
    const float* bias = p.bb[L] + m * F_;
    const float* aggb = g_agg + (size_t)slot * NF;

    int tid = threadIdx.x;
    int h = tid >> 6, d = tid & 63;
    unsigned long long wp[HID_ / 2];
#pragma unroll
    for (int q = 0; q < HID_ / 2; q++)
        wp[q] = packf2(W[(2 * q) * F_ + h * 64 + d], W[(2 * q + 1) * F_ + h * 64 + d]);
    float bv = bias[tid];
    int n0 = blockIdx.x * 32;
    for (int idx = tid; idx < 32 * 256; idx += 256) {
        int r = idx >> 8, j = idx & 255;
        int kk = j >> 2, hh = j & 3;
        float v = (n0 + r < N_) ? aggb[(size_t)(n0 + r) * F_ + j] : 0.f;
        sagg[r * 272 + hh * 68 + kk] = v;
    }
    __syncthreads();
    int rmax = min(32, N_ - n0);
    for (int r = 0; r < rmax; r++) {
        const ulonglong2* ap = (const ulonglong2*)(sagg + r * 272 + h * 68);
        unsigned long long acc = 0ull;
#pragma unroll
        for (int q = 0; q < 16; q++) {
            ulonglong2 av = ap[q];
            fma2(acc, av.x, wp[2 * q]);
            fma2(acc, av.y, wp[2 * q + 1]);
        }
        float o = unpack_sum(acc) + bv;
        g_emb[(size_t)slot * NF + (size_t)(n0 + r) * F_ + tid] = o > 0.f ? o : expm1f(o);
    }
}

// ---------------------------------------------------------------------------
// W1 prep: bf16x2-pack all 3 W1 matrices (y = slot); zeros wsum[slot]
// ---------------------------------------------------------------------------
__global__ void k_prepW1b3(const float* __restrict__ W1a,
                           const float* __restrict__ W1b,
                           const float* __restrict__ W1f) {
    int z = blockIdx.y;
    const float* W1 = (z == 0) ? W1a : (z == 1) ? W1b : W1f;
    int j = blockIdx.x * 256 + threadIdx.x;
    if (j < W1HALF) {
        int pp = j >> 7, c = j & 127;
        g_W1bf[z * W1HALF + j] = pack_bf2(W1[(2 * pp) * SAH_ + c], W1[(2 * pp + 1) * SAH_ + c]);
    }
    if (blockIdx.x == 0 && threadIdx.x < 4) g_wsum[z][threadIdx.x] = 0.f;
}

// ---------------------------------------------------------------------------
// Semantic-attention score GEMM, bf16; batched over stages via blockIdx.z
// ---------------------------------------------------------------------------
__global__ void __launch_bounds__(256) k_wscore_tc(int sel, LP p,
                                                   const float* __restrict__ b1f,
                                                   const float* __restrict__ w2f) {
    __shared__ unsigned int sA[128 * 18];
    __shared__ unsigned int sB[128 * 18];
    __shared__ float s_b1[SAH_], s_w2[SAH_];
    __shared__ float sred[8];

    int tid = threadIdx.x, lane = tid & 31, w = tid >> 5;
    int m = blockIdx.y;
    int z = blockIdx.z;
    int stage = sel ? 2 : z;
    int n0 = blockIdx.x * 128;
    const float* Z = sel ? (g_hl + (size_t)m * NF)
                         : (g_emb + (size_t)(z * 3 + m) * NF);
    const unsigned int* W1p = g_W1bf + (sel ? 2 : z) * W1HALF;
    const float* b1 = sel ? b1f : p.b1[z];
    const float* w2 = sel ? w2f : p.w2[z];
    if (tid < SAH_) { s_b1[tid] = b1[tid]; s_w2[tid] = w2[tid]; }

    float acc[16][4];
#pragma unroll
    for (int t = 0; t < 16; t++)
#pragma unroll
        for (int j = 0; j < 4; j++) acc[t][j] = 0.f;

    int g4 = lane >> 2, tg = lane & 3;
    int ar0 = w * 16 + g4, ar1 = ar0 + 8;

    for (int f0 = 0; f0 < F_; f0 += 32) {
        int p0 = f0 >> 1;
        __syncthreads();
        for (int i = tid; i < 128 * 16; i += 256) {
            int r = i >> 4, pp = i & 15;
            int n = n0 + r;
            float2 v = make_float2(0.f, 0.f);
            if (n < N_) v = *(const float2*)&Z[(size_t)n * F_ + f0 + pp * 2];
            sA[r * 18 + pp] = pack_bf2(v.x, v.y);
        }
        for (int i = tid; i < 128 * 16; i += 256) {
            int c = i & 127, pp = i >> 7;
            sB[c * 18 + pp] = W1p[(p0 + pp) * 128 + c];
        }
        __syncthreads();
#pragma unroll
        for (int s = 0; s < 2; s++) {
            int base = s * 8;
            unsigned int a0 = sA[ar0 * 18 + base + tg];
            unsigned int a1 = sA[ar1 * 18 + base + tg];
            unsigned int a2 = sA[ar0 * 18 + base + tg + 4];
            unsigned int a3 = sA[ar1 * 18 + base + tg + 4];
#pragma unroll
            for (int t = 0; t < 16; t++) {
                int c = t * 8 + g4;
                unsigned int b0 = sB[c * 18 + base + tg];
                unsigned int b1v = sB[c * 18 + base + tg + 4];
                mma_bf16(acc[t][0], acc[t][1], acc[t][2], acc[t][3],
                         a0, a1, a2, a3, b0, b1v);
            }
        }
    }

    float tot = 0.f;
    bool v0 = (n0 + ar0) < N_, v1 = (n0 + ar1) < N_;
#pragma unroll
    for (int t = 0; t < 16; t++) {
        int c0 = t * 8 + tg * 2, c1 = c0 + 1;
        float bb0 = s_b1[c0], bb1 = s_b1[c1];
        float ww0 = s_w2[c0], ww1 = s_w2[c1];
        if (v0) tot += tanh_fast(acc[t][0] + bb0) * ww0 + tanh_fast(acc[t][1] + bb1) * ww1;
        if (v1) tot += tanh_fast(acc[t][2] + bb0) * ww0 + tanh_fast(acc[t][3] + bb1) * ww1;
    }
#pragma unroll
    for (int o = 16; o > 0; o >>= 1) tot += __shfl_xor_sync(0xffffffffu, tot, o);
    if (lane == 0) sred[w] = tot;
    __syncthreads();
    if (tid == 0) {
        float s = 0.f;
#pragma unroll
        for (int i = 0; i < 8; i++) s += sred[i];
        atomicAdd(&g_wsum[stage][m], s);
    }
}

__global__ void k_beta2() {
    if (threadIdx.x < 2) {
        int stage = threadIdx.x;
        float w[3];
        float mx = -1e30f;
        for (int m = 0; m < 3; m++) { w[m] = g_wsum[stage][m] / (float)N_; mx = fmaxf(mx, w[m]); }
        float s = 0.f;
        for (int m = 0; m < 3; m++) { w[m] = __expf(w[m] - mx); s += w[m]; }
        for (int m = 0; m < 3; m++) g_beta[stage][m] = w[m] / s;
    }
}
__global__ void k_betaF() {
    if (threadIdx.x == 0) {
        float w[2];
        float mx = -1e30f;
        for (int m = 0; m < 2; m++) { w[m] = g_wsum[2][m] / (float)N_; mx = fmaxf(mx, w[m]); }
        float s = 0.f;
        for (int m = 0; m < 2; m++) { w[m] = __expf(w[m] - mx); s += w[m]; }
        for (int m = 0; m < 2; m++) g_beta[2][m] = w[m] / s;
    }
}

__global__ void k_combine01() {
    int stage = blockIdx.y;
    size_t i = ((size_t)blockIdx.x * 256 + threadIdx.x) * 4;
    if (i >= NF) return;
    const float* base = g_emb + (size_t)stage * 3 * NF;
    float b0 = g_beta[stage][0], b1 = g_beta[stage][1], b2 = g_beta[stage][2];
    float4 v0 = *(const float4*)&base[i];
    float4 v1 = *(const float4*)&base[NF + i];
    float4 v2 = *(const float4*)&base[2 * NF + i];
    float4 r;
    r.x = b0 * v0.x + b1 * v1.x + b2 * v2.x;
    r.y = b0 * v0.y + b1 * v1.y + b2 * v2.y;
    r.z = b0 * v0.z + b1 * v1.z + b2 * v2.z;
    r.w = b0 * v0.w + b1 * v1.w + b2 * v2.w;
    *(float4*)&g_hl[stage * NF + i] = r;
}

// ---------------------------------------------------------------------------
// Fused final combine + prediction
// ---------------------------------------------------------------------------
__global__ void __launch_bounds__(256) k_predF(const float* __restrict__ W,
                                               const float* __restrict__ b,
                                               float* __restrict__ out,
                                               float* __restrict__ dup) {
    __shared__ float sW[F_ * OUT_];
    __shared__ __align__(16) float sr[16 * F_];
    int tid = threadIdx.x;
    for (int i = tid; i < F_ * OUT_; i += 256) sW[i] = W[i];
    float b0 = g_beta[2][0], b1 = g_beta[2][1];
    int n0 = blockIdx.x * 16;
    for (int i = tid; i < 16 * F_ / 4; i += 256) {
        int r = (i * 4) >> 8, f = (i * 4) & 255;
        int n = n0 + r;
        float4 rv = make_float4(0.f, 0.f, 0.f, 0.f);
        if (n < N_) {
            float4 v0 = *(const float4*)&g_hl[(size_t)n * F_ + f];
            float4 v1 = *(const float4*)&g_hl[NF + (size_t)n * F_ + f];
            rv.x = b0 * v0.x + b1 * v1.x;
            rv.y = b0 * v0.y + b1 * v1.y;
            rv.z = b0 * v0.z + b1 * v1.z;
            rv.w = b0 * v0.w + b1 * v1.w;
            if (dup) *(float4*)&dup[(size_t)n * F_ + f] = rv;
        }
        *(float4*)&sr[r * F_ + f] = rv;
    }
    __syncthreads();
    int node = n0 + (tid >> 4);
    int o = tid & 15;
    if (node >= N_) return;
    const float* hr = sr + (tid >> 4) * F_;
    float acc = b[o];
#pragma unroll 8
    for (int f = 0; f < F_; f++) acc += hr[f] * sW[f * OUT_ + o];
    out[(size_t)node * OUT_ + o] = acc;
}

// ---------------------------------------------------------------------------
// Host launcher — single stream, graph-capturable
// ---------------------------------------------------------------------------
extern "C" void kernel_launch(void* const* d_in, const int* in_sizes, int n_in,
                              void* d_out, int out_size) {
    const float* h = (const float*)d_in[0];
    G4 a;
    a.s[0] = (const int*)d_in[1]; a.d[0] = (const int*)d_in[2];
    a.s[1] = (const int*)d_in[3]; a.d[1] = (const int*)d_in[4];
    a.s[2] = (const int*)d_in[5]; a.d[2] = (const int*)d_in[6];
    a.s[3] = (const int*)d_in[7]; a.d[3] = (const int*)d_in[8];
    a.E[0] = in_sizes[1]; a.E[1] = in_sizes[3]; a.E[2] = in_sizes[5]; a.E[3] = in_sizes[7];
    const float* fcW = (const float*)d_in[10];
    LP p;
    p.W[0]  = (const float*)d_in[11]; p.W[1]  = (const float*)d_in[18];
    p.al[0] = (const float*)d_in[12]; p.al[1] = (const float*)d_in[19];
    p.ar[0] = (const float*)d_in[13]; p.ar[1] = (const float*)d_in[20];
    p.bb[0] = (const float*)d_in[14]; p.bb[1] = (const float*)d_in[21];
    const float* saW1[2] = {(const float*)d_in[15], (const float*)d_in[22]};
    p.b1[0] = (const float*)d_in[16]; p.b1[1] = (const float*)d_in[23];
    p.w2[0] = (const float*)d_in[17]; p.w2[1] = (const float*)d_in[24];
    const float* saW1f = (const float*)d_in[25];
    const float* sab1f = (const float*)d_in[26];
    const float* saw2f = (const float*)d_in[27];
    const float* predW = (const float*)d_in[28];
    const float* predb = (const float*)d_in[29];
    float* out = (float*)d_out;

    int maxE = a.E[0];
    for (int g = 1; g < 4; g++) if (a.E[g] > maxE) maxE = a.E[g];
    const int CMB = (int)((NF / 4 + 255) / 256);

    k_fc<<<(N_ + 15) / 16, 256>>>(h, fcW);
    k_prew6<<<6, 256>>>(p);
    k_zerocnt4<<<SCB4, 256>>>();
    k_hist4<<<dim3((maxE + 255) / 256, 4), 256>>>(a);
    k_eler6<<<dim3((N_ + 31) / 32, 6), 256>>>();
    k_scan1b<<<SCB4, 256>>>();
    k_scan2b<<<1, 1024>>>();
    k_scan3b<<<SCB4, 256>>>();
    k_scatter4<<<dim3((maxE + 255) / 256, 4), 256>>>(a);

    k_conv6<<<dim3((N_ + 7) / 8, 6), 256>>>();
    k_post6<<<dim3((N_ + 31) / 32, 6), 256>>>(p);

    k_prepW1b3<<<dim3((W1HALF + 255) / 256, 3), 256>>>(saW1[0], saW1[1], saW1f);
    k_wscore_tc<<<dim3(WSB_N, 3, 2), 256>>>(0, p, nullptr, nullptr);
    k_beta2<<<1, 32>>>();
    k_combine01<<<dim3(CMB, 2), 256>>>();

    k_wscore_tc<<<dim3(WSB_N, 2, 1), 256>>>(1, p, sab1f, saw2f);
    k_betaF<<<1, 32>>>();
    float* dup = (out_size >= N_ * (OUT_ + F_)) ? out + (size_t)N_ * OUT_ : nullptr;
    k_predF<<<(N_ + 15) / 16, 256>>>(predW, predb, out, dup);
}